// round 1
// baseline (speedup 1.0000x reference)
#include <cuda_runtime.h>
#include <cstdint>
#include <cstdio>

// Anchor3DHead: three 1x1 convs over x[B=4, C=384, H=248, W=216].
// Equivalent to out[o, p] = sum_c w[c][o] * x[c][p] (+ bias), o in [0,72),
// with output sections (cls 18 | reg 42 | dir 12) concatenated:
//   out = [ cls (B,18,H,W) | reg (B,42,H,W) | dir (B,12,H,W) ]  (flattened)
//
// Strategy (round 1 baseline): per-pixel GEMV with fused weights in SMEM,
// packed fp32x2 FMAs (fma.rn.f32x2) so the FMA pipe does 2 FMAs/instr.

namespace {
constexpr int Cdim = 384;
constexpr int OCLS = 18, OREG = 42, ODIR = 12;
constexpr int OALL = OCLS + OREG + ODIR;        // 72
constexpr int Hh = 248, Ww = 216;
constexpr int HW = Hh * Ww;                      // 53568
constexpr int Bb = 4;
constexpr int THREADS = 128;
constexpr int WSH_BYTES = Cdim * OALL * 4;       // 110592
}

__global__ void __launch_bounds__(THREADS, 2)
anchor_head_kernel(const float* __restrict__ x,
                   const float* __restrict__ wc, const float* __restrict__ bc,
                   const float* __restrict__ wr, const float* __restrict__ br,
                   const float* __restrict__ wd, const float* __restrict__ bd,
                   float* __restrict__ out)
{
    extern __shared__ float wsh[];   // [Cdim][OALL], row-major, 288 B/row (16B aligned)
    const int tid = threadIdx.x;

    // Cooperative load of fused weight matrix into SMEM (runs once per block;
    // total weight footprint is 110 KB so all re-reads hit L2).
    for (int idx = tid; idx < Cdim * OALL; idx += THREADS) {
        const int c = idx / OALL;
        const int o = idx - c * OALL;
        float v;
        if (o < OCLS)             v = wc[c * OCLS + o];
        else if (o < OCLS + OREG) v = wr[c * OREG + (o - OCLS)];
        else                      v = wd[c * ODIR + (o - OCLS - OREG)];
        wsh[idx] = v;
    }
    __syncthreads();

    const int b = blockIdx.y;
    const int p = blockIdx.x * THREADS + tid;
    if (p >= HW) return;

    const float* xp = x + (size_t)b * Cdim * HW + p;

    // 36 packed accumulators: acc[i] holds outputs (2i, 2i+1) for this pixel.
    unsigned long long acc[OALL / 2];
#pragma unroll
    for (int i = 0; i < OALL / 2; ++i) acc[i] = 0ull;

    unsigned sbase;
    asm("{ .reg .u64 t; cvta.to.shared.u64 t, %1; cvt.u32.u64 %0, t; }"
        : "=r"(sbase) : "l"(wsh));

    // Software-pipelined x loads: prefetch next 4 channels while computing 4.
    float xb[4];
#pragma unroll
    for (int j = 0; j < 4; ++j) xb[j] = xp[(size_t)j * HW];

    for (int c0 = 0; c0 < Cdim; c0 += 4) {
        float xn[4] = {0.f, 0.f, 0.f, 0.f};
        if (c0 + 4 < Cdim) {
#pragma unroll
            for (int j = 0; j < 4; ++j) xn[j] = xp[(size_t)(c0 + 4 + j) * HW];
        }
#pragma unroll
        for (int j = 0; j < 4; ++j) {
            const unsigned xu = __float_as_uint(xb[j]);
            unsigned long long x2;
            asm("mov.b64 %0, {%1, %1};" : "=l"(x2) : "r"(xu));
            const unsigned row = sbase + (unsigned)(c0 + j) * (OALL * 4);
#pragma unroll
            for (int i = 0; i < 18; ++i) {
                unsigned long long w0, w1;
                asm("ld.shared.v2.b64 {%0, %1}, [%2];"
                    : "=l"(w0), "=l"(w1) : "r"(row + i * 16));
                asm("fma.rn.f32x2 %0, %1, %2, %0;"
                    : "+l"(acc[2 * i])     : "l"(x2), "l"(w0));
                asm("fma.rn.f32x2 %0, %1, %2, %0;"
                    : "+l"(acc[2 * i + 1]) : "l"(x2), "l"(w1));
            }
        }
#pragma unroll
        for (int j = 0; j < 4; ++j) xb[j] = xn[j];
    }

    // Unpack accumulators.
    float r[OALL];
#pragma unroll
    for (int i = 0; i < OALL / 2; ++i) {
        unsigned lo, hi;
        asm("mov.b64 {%0, %1}, %2;" : "=r"(lo), "=r"(hi) : "l"(acc[i]));
        r[2 * i]     = __uint_as_float(lo);
        r[2 * i + 1] = __uint_as_float(hi);
    }

    // Epilogue: add bias, write three sections (coalesced over p within warp).
    float* o0 = out + (size_t)b * OCLS * HW + p;
#pragma unroll
    for (int o = 0; o < OCLS; ++o) o0[(size_t)o * HW] = r[o] + bc[o];

    float* o1 = out + (size_t)Bb * OCLS * HW + (size_t)b * OREG * HW + p;
#pragma unroll
    for (int o = 0; o < OREG; ++o) o1[(size_t)o * HW] = r[OCLS + o] + br[o];

    float* o2 = out + (size_t)Bb * (OCLS + OREG) * HW + (size_t)b * ODIR * HW + p;
#pragma unroll
    for (int o = 0; o < ODIR; ++o) o2[(size_t)o * HW] = r[OCLS + OREG + o] + bd[o];
}

extern "C" void kernel_launch(void* const* d_in, const int* in_sizes, int n_in,
                              void* d_out, int out_size)
{
    // Identify inputs robustly by element count (all sizes distinct).
    const float *x = nullptr, *wc = nullptr, *bc = nullptr,
                *wr = nullptr, *br = nullptr, *wd = nullptr, *bd = nullptr;
    for (int i = 0; i < n_in; ++i) {
        const float* ptr = (const float*)d_in[i];
        switch (in_sizes[i]) {
            case Bb * Cdim * HW:  x  = ptr; break;   // 82,280,448
            case Cdim * OCLS:     wc = ptr; break;   // 6912
            case OCLS:            bc = ptr; break;   // 18
            case Cdim * OREG:     wr = ptr; break;   // 16128
            case OREG:            br = ptr; break;   // 42
            case Cdim * ODIR:     wd = ptr; break;   // 4608
            case ODIR:            bd = ptr; break;   // 12
            default: break;
        }
    }

    // Opt-in to >48KB dynamic SMEM (idempotent; not a stream-ordered call).
    cudaFuncSetAttribute(anchor_head_kernel,
                         cudaFuncAttributeMaxDynamicSharedMemorySize, WSH_BYTES);

    dim3 grid((HW + THREADS - 1) / THREADS, Bb);
    anchor_head_kernel<<<grid, THREADS, WSH_BYTES>>>(
        x, wc, bc, wr, br, wd, bd, (float*)d_out);
}